// round 1
// baseline (speedup 1.0000x reference)
#include <cuda_runtime.h>
#include <cstdint>

#define NP 256
#define NG 1024
#define F  128
#define EPSV 1e-5f

#define TP 32
#define TG 64
#define KC 64

// ---------------- device scratch (static, allocation-free) ----------------
__device__ float2 d_PT[F * NP];   // [f][p] : probe value pre-scaled by (w'_0, w'_1), pair-interleaved
__device__ float  d_GT[F * NG];   // [f][g] : gallery transposed
__device__ float2 d_A[NP];        // A[p,c] = sum_f w'_c p^2
__device__ float2 d_B[NG];        // B[g,c] = sum_f w'_c g^2
__device__ float2 d_K;            // K[c]   = sum_f W[c,f]*(beta - mu*inv) + b[c]

// ---------------- f32x2 packed helpers ----------------
__device__ __forceinline__ unsigned long long fma2(unsigned long long a,
                                                   unsigned long long b,
                                                   unsigned long long c) {
    unsigned long long d;
    asm("fma.rn.f32x2 %0, %1, %2, %3;" : "=l"(d) : "l"(a), "l"(b), "l"(c));
    return d;
}
__device__ __forceinline__ unsigned long long dup2(float x) {
    unsigned long long d;
    asm("mov.b64 %0, {%1, %1};" : "=l"(d) : "f"(x));
    return d;
}
__device__ __forceinline__ float2 unpack2(unsigned long long v) {
    float2 r;
    asm("mov.b64 {%0, %1}, %2;" : "=f"(r.x), "=f"(r.y) : "l"(v));
    return r;
}

// ---------------- block reduction (128 threads, 2 lanes) ----------------
__device__ __forceinline__ void freduce2(float a, float b, float2* out) {
    #pragma unroll
    for (int o = 16; o > 0; o >>= 1) {
        a += __shfl_down_sync(0xffffffffu, a, o);
        b += __shfl_down_sync(0xffffffffu, b, o);
    }
    __shared__ float sb[8];
    int w = threadIdx.x >> 5, l = threadIdx.x & 31;
    if (l == 0) { sb[w] = a; sb[4 + w] = b; }
    __syncthreads();
    if (threadIdx.x == 0) {
        out->x = sb[0] + sb[1] + sb[2] + sb[3];
        out->y = sb[4] + sb[5] + sb[6] + sb[7];
    }
}

// ---------------- prep: fold BN into W, scale/transpose probes, transpose gallery ----------------
__global__ void __launch_bounds__(128) prep_kernel(
    const float* __restrict__ probe, const float* __restrict__ gal,
    const float* __restrict__ bnw, const float* __restrict__ bnb,
    const float* __restrict__ bnm, const float* __restrict__ bnv,
    const float* __restrict__ W, const float* __restrict__ bias)
{
    const int f = threadIdx.x;                  // 0..127
    const float inv = bnw[f] * rsqrtf(bnv[f] + EPSV);
    const float w0 = W[f] * inv;
    const float w1 = W[F + f] * inv;
    const int bid = blockIdx.x;

    if (bid < NP) {
        const int p = bid;
        const float x = probe[p * F + f];
        float2 pv = make_float2(x * w0, x * w1);
        d_PT[f * NP + p] = pv;
        freduce2(pv.x * x, pv.y * x, &d_A[p]);
    } else if (bid < NP + NG) {
        const int g = bid - NP;
        const float x = gal[g * F + f];
        d_GT[f * NG + g] = x;
        freduce2(w0 * x * x, w1 * x * x, &d_B[g]);
    } else {
        const float off = bnb[f] - bnm[f] * inv;
        float2 r;
        freduce2(W[f] * off, W[F + f] * off, &r);
        if (threadIdx.x == 0) d_K = make_float2(r.x + bias[0], r.y + bias[1]);
    }
}

// ---------------- main: out = A + B + K - 2*cross ----------------
__global__ void __launch_bounds__(256) cls_kernel(float* __restrict__ out) {
    __shared__ float2 sP[KC][TP];   // 16 KB
    __shared__ float  sG[KC][TG];   // 16 KB

    const int bp = blockIdx.y * TP;
    const int bg = blockIdx.x * TG;
    const int tid = threadIdx.x;
    const int ty = tid >> 4;        // 0..15 -> probe pair
    const int tx = tid & 15;        // 0..15 -> gallery quad
    const int tp = ty * 2;
    const int tg = tx * 4;

    unsigned long long acc[2][4];
    #pragma unroll
    for (int i = 0; i < 2; i++)
        #pragma unroll
        for (int j = 0; j < 4; j++) acc[i][j] = 0ull;

    for (int k0 = 0; k0 < F; k0 += KC) {
        // Load tiles: KC rows, each 16 float4 for both sP and sG. 1024 float4 each / 256 thr.
        #pragma unroll
        for (int it = 0; it < 4; it++) {
            const int idx = tid + it * 256;
            const int r = idx >> 4, c = idx & 15;
            ((float4*)&sP[r][0])[c] = ((const float4*)(d_PT + (size_t)(k0 + r) * NP + bp))[c];
            ((float4*)&sG[r][0])[c] = ((const float4*)(d_GT + (size_t)(k0 + r) * NG + bg))[c];
        }
        __syncthreads();

        #pragma unroll 8
        for (int f = 0; f < KC; f++) {
            const ulonglong2 pv = *(const ulonglong2*)&sP[f][tp];   // probes tp, tp+1 (class-pairs)
            const float4 gv = *(const float4*)&sG[f][tg];
            const unsigned long long g0 = dup2(gv.x);
            const unsigned long long g1 = dup2(gv.y);
            const unsigned long long g2 = dup2(gv.z);
            const unsigned long long g3 = dup2(gv.w);
            acc[0][0] = fma2(pv.x, g0, acc[0][0]);
            acc[0][1] = fma2(pv.x, g1, acc[0][1]);
            acc[0][2] = fma2(pv.x, g2, acc[0][2]);
            acc[0][3] = fma2(pv.x, g3, acc[0][3]);
            acc[1][0] = fma2(pv.y, g0, acc[1][0]);
            acc[1][1] = fma2(pv.y, g1, acc[1][1]);
            acc[1][2] = fma2(pv.y, g2, acc[1][2]);
            acc[1][3] = fma2(pv.y, g3, acc[1][3]);
        }
        __syncthreads();
    }

    // Epilogue: out[p,g,c] = A[p,c] + B[g,c] + K[c] - 2*cross
    const float2 Kc = d_K;
    float2 Bv[4];
    #pragma unroll
    for (int j = 0; j < 4; j++) Bv[j] = d_B[bg + tg + j];

    #pragma unroll
    for (int i = 0; i < 2; i++) {
        const int p = bp + tp + i;
        const float2 Ap = d_A[p];
        const float ax = Ap.x + Kc.x;
        const float ay = Ap.y + Kc.y;
        float4 v0, v1;
        float2 c;
        c = unpack2(acc[i][0]);
        v0.x = fmaf(-2.0f, c.x, ax + Bv[0].x);
        v0.y = fmaf(-2.0f, c.y, ay + Bv[0].y);
        c = unpack2(acc[i][1]);
        v0.z = fmaf(-2.0f, c.x, ax + Bv[1].x);
        v0.w = fmaf(-2.0f, c.y, ay + Bv[1].y);
        c = unpack2(acc[i][2]);
        v1.x = fmaf(-2.0f, c.x, ax + Bv[2].x);
        v1.y = fmaf(-2.0f, c.y, ay + Bv[2].y);
        c = unpack2(acc[i][3]);
        v1.z = fmaf(-2.0f, c.x, ax + Bv[3].x);
        v1.w = fmaf(-2.0f, c.y, ay + Bv[3].y);
        float4* dst = (float4*)(out + ((size_t)p * NG + (bg + tg)) * 2);
        dst[0] = v0;
        dst[1] = v1;
    }
}

// ---------------- launch ----------------
extern "C" void kernel_launch(void* const* d_in, const int* in_sizes, int n_in,
                              void* d_out, int out_size) {
    const float* probe = (const float*)d_in[0];
    const float* gal   = (const float*)d_in[1];
    const float* bnw   = (const float*)d_in[2];
    const float* bnb   = (const float*)d_in[3];
    const float* bnm   = (const float*)d_in[4];
    const float* bnv   = (const float*)d_in[5];
    const float* W     = (const float*)d_in[6];
    const float* bias  = (const float*)d_in[7];
    float* out = (float*)d_out;

    prep_kernel<<<NP + NG + 1, 128>>>(probe, gal, bnw, bnb, bnm, bnv, W, bias);
    dim3 grid(NG / TG, NP / TP);   // (16, 8) = 128 blocks
    cls_kernel<<<grid, 256>>>(out);
}